// round 16
// baseline (speedup 1.0000x reference)
#include <cuda_runtime.h>
#include <cuda_fp16.h>
#include <math.h>
#include <stdint.h>

// Problem dims
#define S   2048
#define Dm  4096
#define HQ  32
#define HK  8
#define HD  128
#define NQ  (HQ*HD)   // 4096
#define NKV (HK*HD)   // 1024
#define NQKV (NQ + 2*NKV)  // 6144

// Scratch (device globals; no allocations allowed)
__device__ __half g_Q[S*NQ];            // Q, roped, [S][4096]
__device__ __half g_K[S*NKV];           // K, roped, [S][1024]
__device__ __half g_Vt[NKV*S];          // V transposed: [1024 d][2048 s]
__device__ __half g_attn[S*NQ];         // attention output, [S][4096]
__device__ __half g_X [S*Dm];           // x as half, [S][4096]
__device__ __half g_W6[NQKV*Dm];        // wq|wk|wv transposed: [6144][4096]
__device__ __half g_Wo[Dm*NQ];          // wo transposed: [4096][4096]

// ---------------------------------------------------------------------------
// helpers
// ---------------------------------------------------------------------------
__device__ __forceinline__ void mma_f16(float c[4], const unsigned a[4],
                                        unsigned b0, unsigned b1) {
    asm volatile(
        "mma.sync.aligned.m16n8k16.row.col.f32.f16.f16.f32 "
        "{%0,%1,%2,%3}, {%4,%5,%6,%7}, {%8,%9}, {%0,%1,%2,%3};"
        : "+f"(c[0]), "+f"(c[1]), "+f"(c[2]), "+f"(c[3])
        : "r"(a[0]), "r"(a[1]), "r"(a[2]), "r"(a[3]), "r"(b0), "r"(b1));
}

__device__ __forceinline__ void ldsm4(unsigned& r0, unsigned& r1,
                                      unsigned& r2, unsigned& r3, uint32_t addr) {
    asm volatile("ldmatrix.sync.aligned.m8n8.x4.shared.b16 {%0,%1,%2,%3}, [%4];"
                 : "=r"(r0), "=r"(r1), "=r"(r2), "=r"(r3) : "r"(addr));
}

__device__ __forceinline__ void cp16(uint32_t dst, const void* src) {
    asm volatile("cp.async.cg.shared.global [%0], [%1], 16;\n" :: "r"(dst), "l"(src));
}
__device__ __forceinline__ void cp_commit() {
    asm volatile("cp.async.commit_group;\n");
}
template<int N> __device__ __forceinline__ void cp_wait() {
    asm volatile("cp.async.wait_group %0;\n" :: "n"(N));
}

// ---------------------------------------------------------------------------
// Mega-prep: one launch does x->half and all 4 weight transposes.
// ---------------------------------------------------------------------------
#define RB_WQ 16384
#define RB_WK 4096
#define RB_WV 4096
#define RB_WO 16384
#define RB_X  2048
#define PREP_BLOCKS (RB_WQ + RB_WK + RB_WV + RB_WO + RB_X)

__device__ __forceinline__ void transp_f2h(const float* __restrict__ src,
                                           __half* __restrict__ dst,
                                           int R, int C, int bx, int by, int tid,
                                           float (*tile)[33]) {
    int c0 = bx*32, r0 = by*32;
    int x = tid & 31, y = tid >> 5;
    #pragma unroll
    for (int i = y; i < 32; i += 8)
        tile[i][x] = src[(size_t)(r0 + i) * C + c0 + x];
    __syncthreads();
    #pragma unroll
    for (int i = y; i < 32; i += 8)
        dst[(size_t)(c0 + i) * R + r0 + x] = __float2half_rn(tile[x][i]);
}

__global__ __launch_bounds__(256)
void prep_kernel(const float* __restrict__ x,
                 const float* __restrict__ wq, const float* __restrict__ wk,
                 const float* __restrict__ wv, const float* __restrict__ wo,
                 __half* __restrict__ Xh, __half* __restrict__ W6,
                 __half* __restrict__ Wot) {
    __shared__ float tile[32][33];
    int bid = blockIdx.x;
    int tid = threadIdx.x;
    if (bid < RB_WQ) {
        transp_f2h(wq, W6, Dm, NQ, bid % 128, bid / 128, tid, tile);
        return;
    }
    bid -= RB_WQ;
    if (bid < RB_WK) {
        transp_f2h(wk, W6 + (size_t)NQ*Dm, Dm, NKV, bid % 32, bid / 32, tid, tile);
        return;
    }
    bid -= RB_WK;
    if (bid < RB_WV) {
        transp_f2h(wv, W6 + (size_t)(NQ+NKV)*Dm, Dm, NKV, bid % 32, bid / 32, tid, tile);
        return;
    }
    bid -= RB_WV;
    if (bid < RB_WO) {
        transp_f2h(wo, Wot, NQ, Dm, bid % 128, bid / 128, tid, tile);
        return;
    }
    bid -= RB_WO;
    {
        const float4* src4 = (const float4*)x;
        #pragma unroll
        for (int j = 0; j < 4; j++) {
            int i = bid*1024 + tid + j*256;
            float4 v = src4[i];
            *(__half2*)&Xh[4*i]     = __floats2half2_rn(v.x, v.y);
            *(__half2*)&Xh[4*i + 2] = __floats2half2_rn(v.z, v.w);
        }
    }
}

// ---------------------------------------------------------------------------
// fp16 tensor-core GEMM, cp.async 5-stage pipeline, ldmatrix fragments.
// C[M,N] = A[M,K] @ Bt[N,K]^T.  128x256 CTA tile, BK=32, 8 warps, each 64x64.
// 1 CTA/SM; warp-tile reuse halves smem crossbar traffic per MAC (the R11
// co-limiter). mode 0: fp32 C out. mode 1: fused QKV epilogue.
// Requires M%128==0, N%256==0, K%32==0.
// ---------------------------------------------------------------------------
#define APITCH 40                 // halves per smem row (32 data + 8 pad)
#define A_HALVES (128*APITCH)     // 5120
#define B_HALVES (256*APITCH)     // 10240
#define STAGE_HALVES (A_HALVES + B_HALVES)   // 15360 halves = 30720 B
#define GSTAGES 5
#define GEMM_SMEM (GSTAGES*STAGE_HALVES*2)   // 153600 B

__global__ __launch_bounds__(256)
void gemm_f16(int M, int N, int K,
              const __half* __restrict__ A,
              const __half* __restrict__ Bt,
              void* __restrict__ Cv, int mode,
              __half* __restrict__ Qp, __half* __restrict__ Kp,
              __half* __restrict__ Vtp,
              const float* __restrict__ fc, const float* __restrict__ fs) {
    extern __shared__ __half smh[];
    const uint32_t smemBase = (uint32_t)__cvta_generic_to_shared(smh);

    const int tid  = threadIdx.x;
    const int lane = tid & 31;
    const int wid  = tid >> 5;
    const int gid  = lane >> 2;
    const int tig  = lane & 3;
    const int warpM = wid >> 2;   // 0..1 (M: 2 x 64)
    const int warpN = wid & 3;    // 0..3 (N: 4 x 64)
    const int m0 = warpM*64;
    const int n0 = warpN*64;

    const int g8 = lane >> 3, r8 = lane & 7;
    const int laneA = ((((g8 & 1) << 3) + r8) * APITCH + ((g8 >> 1) << 3)) * 2;
    const int laneB = ((((g8 >> 1) << 3) + r8) * APITCH + ((g8 & 1) << 3)) * 2;

    const int bx = blockIdx.x;    // N tile (256 wide)
    const int by = blockIdx.y;    // M tile (128 tall)

    const __half* Abase = A  + (size_t)(by*128) * K;
    const __half* Bbase = Bt + (size_t)(bx*256) * K;

    // per k-tile: A 512 chunks16B (128 rows x 4), B 1024 chunks (256 rows x 4)
    auto issue_tile = [&](int t) {
        const int slot = t % GSTAGES;
        const uint32_t stA = smemBase + slot*STAGE_HALVES*2;
        const uint32_t stB = stA + A_HALVES*2;
        const __half* Ag = Abase + t*32;
        const __half* Bg = Bbase + t*32;
        #pragma unroll
        for (int j = 0; j < 2; j++) {
            int e = tid + j*256;
            int row = e >> 2, ch = e & 3;
            cp16(stA + (row*APITCH + ch*8)*2, Ag + (size_t)row*K + ch*8);
        }
        #pragma unroll
        for (int j = 0; j < 4; j++) {
            int e = tid + j*256;
            int row = e >> 2, ch = e & 3;
            cp16(stB + (row*APITCH + ch*8)*2, Bg + (size_t)row*K + ch*8);
        }
    };

    float c[4][8][4];
    #pragma unroll
    for (int i = 0; i < 4; i++)
        #pragma unroll
        for (int j = 0; j < 8; j++)
            #pragma unroll
            for (int r = 0; r < 4; r++) c[i][j][r] = 0.f;

    const int nt = K / 32;

    #pragma unroll
    for (int t = 0; t < GSTAGES-1; t++) {
        if (t < nt) issue_tile(t);
        cp_commit();
    }

    for (int t = 0; t < nt; t++) {
        cp_wait<GSTAGES-2>();
        __syncthreads();

        if (t + GSTAGES-1 < nt) issue_tile(t + GSTAGES-1);
        cp_commit();

        const int slot = t % GSTAGES;
        const uint32_t slotA = smemBase + slot*STAGE_HALVES*2;
        const uint32_t slotB = slotA + A_HALVES*2;

        #pragma unroll
        for (int hh = 0; hh < 2; hh++) {
            const int ks = hh * 16;
            unsigned af[4][4], bf[8][2];
            #pragma unroll
            for (int mf = 0; mf < 4; mf++)
                ldsm4(af[mf][0], af[mf][1], af[mf][2], af[mf][3],
                      slotA + ((m0 + mf*16)*APITCH + ks)*2 + laneA);
            #pragma unroll
            for (int nf2 = 0; nf2 < 8; nf2 += 2)
                ldsm4(bf[nf2][0], bf[nf2][1], bf[nf2+1][0], bf[nf2+1][1],
                      slotB + ((n0 + nf2*8)*APITCH + ks)*2 + laneB);
            #pragma unroll
            for (int mf = 0; mf < 4; mf++)
                #pragma unroll
                for (int nf = 0; nf < 8; nf++)
                    mma_f16(c[mf][nf], af[mf], bf[nf][0], bf[nf][1]);
        }
    }

    // ---- epilogue ----
    if (mode == 0) {
        float* Cf = (float*)Cv;
        #pragma unroll
        for (int mf = 0; mf < 4; mf++) {
            int row0 = by*128 + m0 + mf*16 + gid;
            #pragma unroll
            for (int nf = 0; nf < 8; nf++) {
                int col = bx*256 + n0 + nf*8 + tig*2;
                *(float2*)&Cf[(size_t)row0 * N + col] =
                    make_float2(c[mf][nf][0], c[mf][nf][1]);
                *(float2*)&Cf[(size_t)(row0+8) * N + col] =
                    make_float2(c[mf][nf][2], c[mf][nf][3]);
            }
        }
    } else {
        #pragma unroll
        for (int mf = 0; mf < 4; mf++) {
            int s0 = by*128 + m0 + mf*16 + gid;
            int s1 = s0 + 8;
            #pragma unroll
            for (int nf = 0; nf < 8; nf++) {
                int gc = bx*256 + n0 + nf*8 + tig*2;
                float v0 = c[mf][nf][0], v1 = c[mf][nf][1];
                float v2 = c[mf][nf][2], v3 = c[mf][nf][3];
                if (gc < NQ) {                      // Q with RoPE
                    int i = (gc & 127) >> 1;
                    float c0 = fc[s0*64+i], sn0 = fs[s0*64+i];
                    float c1 = fc[s1*64+i], sn1 = fs[s1*64+i];
                    *(__half2*)&Qp[(size_t)s0*NQ + gc] =
                        __floats2half2_rn(v0*c0 - v1*sn0, v0*sn0 + v1*c0);
                    *(__half2*)&Qp[(size_t)s1*NQ + gc] =
                        __floats2half2_rn(v2*c1 - v3*sn1, v2*sn1 + v3*c1);
                } else if (gc < NQ + NKV) {         // K with RoPE
                    int d = gc - NQ;
                    int i = (d & 127) >> 1;
                    float c0 = fc[s0*64+i], sn0 = fs[s0*64+i];
                    float c1 = fc[s1*64+i], sn1 = fs[s1*64+i];
                    *(__half2*)&Kp[(size_t)s0*NKV + d] =
                        __floats2half2_rn(v0*c0 - v1*sn0, v0*sn0 + v1*c0);
                    *(__half2*)&Kp[(size_t)s1*NKV + d] =
                        __floats2half2_rn(v2*c1 - v3*sn1, v2*sn1 + v3*c1);
                } else {                            // V, transposed store
                    int d = gc - (NQ + NKV);
                    Vtp[(size_t)d*S + s0]     = __float2half_rn(v0);
                    Vtp[(size_t)(d+1)*S + s0] = __float2half_rn(v1);
                    Vtp[(size_t)d*S + s1]     = __float2half_rn(v2);
                    Vtp[(size_t)(d+1)*S + s1] = __float2half_rn(v3);
                }
            }
        }
    }
}

// ---------------------------------------------------------------------------
// Flash attention, fp16 MMA + ldmatrix. BQ=128, BKV=64. 8 warps. (unchanged)
// ---------------------------------------------------------------------------
#define KP 136
#define VP 72
#define PP 72
#define KVT (64*KP)
#define VTT (128*VP)
#define PS_OFF (2*KVT + 2*VTT)
#define FLASH_SMEM ((PS_OFF + 128*PP) * 2)   // 90112 B

__global__ __launch_bounds__(256)
void flash_f16(const __half* __restrict__ Q,
               const __half* __restrict__ K,
               const __half* __restrict__ Vt,
               __half* __restrict__ O) {
    extern __shared__ __half smh[];
    __half* Ks  = smh;
    __half* Ps  = smh + PS_OFF;

    const int qb  = gridDim.x - 1 - blockIdx.x;
    const int h   = blockIdx.y;
    const int kh  = h >> 2;
    const int tid = threadIdx.x;
    const int lane = tid & 31;
    const int wid  = tid >> 5;
    const int gid  = lane >> 2;
    const int tig  = lane & 3;
    const int m0   = wid * 16;
    const float scale = 0.08838834764831845f;

    const uint32_t smemBase = (uint32_t)__cvta_generic_to_shared(smh);
    const __half* Vkh = Vt + (size_t)(kh*HD) * S;

    const int g8 = lane >> 3, r8 = lane & 7;
    const int laneAK = ((((g8 & 1) << 3) + r8) * KP + ((g8 >> 1) << 3)) * 2;
    const int laneBK = ((((g8 >> 1) << 3) + r8) * KP + ((g8 & 1) << 3)) * 2;
    const int laneAP = ((((g8 & 1) << 3) + r8) * PP + ((g8 >> 1) << 3)) * 2;
    const int laneBV = ((((g8 >> 1) << 3) + r8) * VP + ((g8 & 1) << 3)) * 2;

    #pragma unroll
    for (int i = 0; i < 8; i++) {
        int e = tid + i*256;
        int row = e >> 4;
        int ch  = e & 15;
        *(float4*)&Ks[row*KP + ch*8] =
            *(const float4*)&Q[(size_t)(qb*128 + row)*NQ + h*HD + ch*8];
    }
    __syncthreads();

    unsigned qf[8][4];
    #pragma unroll
    for (int ks = 0; ks < 8; ks++)
        ldsm4(qf[ks][0], qf[ks][1], qf[ks][2], qf[ks][3],
              smemBase + (m0*KP + ks*16)*2 + laneAK);
    __syncthreads();

    float of[16][4];
    #pragma unroll
    for (int n = 0; n < 16; n++)
        #pragma unroll
        for (int r = 0; r < 4; r++) of[n][r] = 0.f;
    float mrow0 = -INFINITY, mrow1 = -INFINITY;
    float lrow0 = 0.f, lrow1 = 0.f;

    const int nkv = 2*qb + 2;

    auto issue_tile = [&](int kb) {
        int buf = kb & 1;
        int kv0 = kb * 64;
        #pragma unroll
        for (int j = 0; j < 4; j++) {
            int e = tid + j*256;
            int row = e >> 4;
            int ch  = e & 15;
            cp16(smemBase + (buf*KVT + row*KP + ch*8)*2,
                 &K[(size_t)(kv0+row)*NKV + kh*HD + ch*8]);
        }
        #pragma unroll
        for (int j = 0; j < 4; j++) {
            int e = tid + j*256;
            int d  = e >> 3;
            int ch = e & 7;
            cp16(smemBase + (2*KVT + buf*VTT + d*VP + ch*8)*2,
                 &Vkh[(size_t)d*S + kv0 + ch*8]);
        }
    };

    issue_tile(0); cp_commit();
    issue_tile(1); cp_commit();

    const int grow0 = qb*128 + m0 + gid;
    const int grow1 = grow0 + 8;

    for (int kb = 0; kb < nkv; kb++) {
        const int buf = kb & 1;
        const int kv0 = kb * 64;
        cp_wait<1>();
        __syncthreads();

        float c[8][4];
        #pragma unroll
        for (int nf = 0; nf < 8; nf++)
            #pragma unroll
            for (int r = 0; r < 4; r++) c[nf][r] = 0.f;

        const uint32_t kbAddr = smemBase + buf*KVT*2;
        #pragma unroll
        for (int ks = 0; ks < 8; ks++) {
            #pragma unroll
            for (int nf2 = 0; nf2 < 8; nf2 += 2) {
                unsigned b0, b1, b2, b3;
                ldsm4(b0, b1, b2, b3, kbAddr + (nf2*8*KP + ks*16)*2 + laneBK);
                mma_f16(c[nf2],   qf[ks], b0, b1);
                mma_f16(c[nf2+1], qf[ks], b2, b3);
            }
        }

        const bool needmask = (kb >= 2*qb);
        #pragma unroll
        for (int nf = 0; nf < 8; nf++) {
            int gc = kv0 + nf*8 + 2*tig;
            c[nf][0] *= scale; c[nf][1] *= scale;
            c[nf][2] *= scale; c[nf][3] *= scale;
            if (needmask) {
                if (gc   > grow0) c[nf][0] = -INFINITY;
                if (gc+1 > grow0) c[nf][1] = -INFINITY;
                if (gc   > grow1) c[nf][2] = -INFINITY;
                if (gc+1 > grow1) c[nf][3] = -INFINITY;
            }
        }

        float mx0 = -INFINITY, mx1 = -INFINITY;
        #pragma unroll
        for (int nf = 0; nf < 8; nf++) {
            mx0 = fmaxf(mx0, fmaxf(c[nf][0], c[nf][1]));
            mx1 = fmaxf(mx1, fmaxf(c[nf][2], c[nf][3]));
        }
        mx0 = fmaxf(mx0, __shfl_xor_sync(0xffffffffu, mx0, 1));
        mx0 = fmaxf(mx0, __shfl_xor_sync(0xffffffffu, mx0, 2));
        mx1 = fmaxf(mx1, __shfl_xor_sync(0xffffffffu, mx1, 1));
        mx1 = fmaxf(mx1, __shfl_xor_sync(0xffffffffu, mx1, 2));

        float mn0 = fmaxf(mrow0, mx0);
        float mn1 = fmaxf(mrow1, mx1);
        float a0 = __expf(mrow0 - mn0);
        float a1 = __expf(mrow1 - mn1);
        mrow0 = mn0; mrow1 = mn1;

        float s0 = 0.f, s1 = 0.f;
        #pragma unroll
        for (int nf = 0; nf < 8; nf++) {
            c[nf][0] = __expf(c[nf][0] - mn0);
            c[nf][1] = __expf(c[nf][1] - mn0);
            c[nf][2] = __expf(c[nf][2] - mn1);
            c[nf][3] = __expf(c[nf][3] - mn1);
            s0 += c[nf][0] + c[nf][1];
            s1 += c[nf][2] + c[nf][3];
        }
        s0 += __shfl_xor_sync(0xffffffffu, s0, 1);
        s0 += __shfl_xor_sync(0xffffffffu, s0, 2);
        s1 += __shfl_xor_sync(0xffffffffu, s1, 1);
        s1 += __shfl_xor_sync(0xffffffffu, s1, 2);
        lrow0 = lrow0*a0 + s0;
        lrow1 = lrow1*a1 + s1;

        #pragma unroll
        for (int nf = 0; nf < 16; nf++) {
            of[nf][0] *= a0; of[nf][1] *= a0;
            of[nf][2] *= a1; of[nf][3] *= a1;
        }

        {
            __half* pr0 = Ps + (m0+gid)*PP + 2*tig;
            __half* pr1 = pr0 + 8*PP;
            #pragma unroll
            for (int nf = 0; nf < 8; nf++) {
                *(__half2*)(pr0 + nf*8) = __floats2half2_rn(c[nf][0], c[nf][1]);
                *(__half2*)(pr1 + nf*8) = __floats2half2_rn(c[nf][2], c[nf][3]);
            }
        }
        __syncwarp();

        const uint32_t psAddr = smemBase + PS_OFF*2;
        const uint32_t vbAddr = smemBase + (2*KVT + buf*VTT)*2;
        #pragma unroll
        for (int ks = 0; ks < 4; ks++) {
            unsigned a[4];
            ldsm4(a[0], a[1], a[2], a[3],
                  psAddr + (m0*PP + ks*16)*2 + laneAP);
            #pragma unroll
            for (int nf2 = 0; nf2 < 16; nf2 += 2) {
                unsigned b0, b1, b2, b3;
                ldsm4(b0, b1, b2, b3, vbAddr + (nf2*8*VP + ks*16)*2 + laneBV);
                mma_f16(of[nf2],   a, b0, b1);
                mma_f16(of[nf2+1], a, b2, b3);
            }
        }

        __syncthreads();
        if (kb + 2 < nkv) issue_tile(kb + 2);
        cp_commit();
    }

    float inv0 = 1.f / lrow0;
    float inv1 = 1.f / lrow1;
    #pragma unroll
    for (int nf = 0; nf < 16; nf++) {
        int col = h*HD + nf*8 + 2*tig;
        *(__half2*)&O[(size_t)grow0 * NQ + col] =
            __floats2half2_rn(of[nf][0]*inv0, of[nf][1]*inv0);
        *(__half2*)&O[(size_t)grow1 * NQ + col] =
            __floats2half2_rn(of[nf][2]*inv1, of[nf][3]*inv1);
    }
}

// ---------------------------------------------------------------------------
// Launch
// ---------------------------------------------------------------------------
extern "C" void kernel_launch(void* const* d_in, const int* in_sizes, int n_in,
                              void* d_out, int out_size) {
    const float* x  = (const float*)d_in[0];
    const float* fc = (const float*)d_in[1];
    const float* fs = (const float*)d_in[2];
    const float* wq = (const float*)d_in[3];
    const float* wk = (const float*)d_in[4];
    const float* wv = (const float*)d_in[5];
    const float* wo = (const float*)d_in[6];
    float* out = (float*)d_out;

    __half *Q, *K, *Vt, *ATT, *Xh, *W6, *Wot;
    cudaGetSymbolAddress((void**)&Q,   g_Q);
    cudaGetSymbolAddress((void**)&K,   g_K);
    cudaGetSymbolAddress((void**)&Vt,  g_Vt);
    cudaGetSymbolAddress((void**)&ATT, g_attn);
    cudaGetSymbolAddress((void**)&Xh,  g_X);
    cudaGetSymbolAddress((void**)&W6,  g_W6);
    cudaGetSymbolAddress((void**)&Wot, g_Wo);

    cudaFuncSetAttribute(flash_f16,
        cudaFuncAttributeMaxDynamicSharedMemorySize, FLASH_SMEM);
    cudaFuncSetAttribute(gemm_f16,
        cudaFuncAttributeMaxDynamicSharedMemorySize, GEMM_SMEM);

    // 1) Mega-prep (one launch)
    prep_kernel<<<PREP_BLOCKS, 256>>>(x, wq, wk, wv, wo, Xh, W6, Wot);

    // 2) Fused QKV projection + RoPE (+ V transpose). N tiles of 256.
    gemm_f16<<<dim3(NQKV/256, S/128), 256, GEMM_SMEM>>>(
        S, NQKV, Dm, Xh, W6, nullptr, 1, Q, K, Vt, fc, fs);

    // 3) Causal GQA flash attention
    flash_f16<<<dim3(S/128, HQ), 256, FLASH_SMEM>>>(Q, K, Vt, ATT);

    // 4) Output projection (fp32 out)
    gemm_f16<<<dim3(Dm/256, S/128), 256, GEMM_SMEM>>>(
        S, Dm, NQ, ATT, Wot, out, 0, nullptr, nullptr, nullptr, nullptr, nullptr);
}

// round 17
// speedup vs baseline: 1.1984x; 1.1984x over previous
#include <cuda_runtime.h>
#include <cuda_fp16.h>
#include <math.h>
#include <stdint.h>

// Problem dims
#define S   2048
#define Dm  4096
#define HQ  32
#define HK  8
#define HD  128
#define NQ  (HQ*HD)   // 4096
#define NKV (HK*HD)   // 1024
#define NQKV (NQ + 2*NKV)  // 6144

// Scratch (device globals; no allocations allowed)
__device__ __half g_Q[S*NQ];            // Q, roped, [S][4096]
__device__ __half g_K[S*NKV];           // K, roped, [S][1024]
__device__ __half g_Vt[NKV*S];          // V transposed: [1024 d][2048 s]
__device__ __half g_attn[S*NQ];         // attention output, [S][4096]
__device__ __half g_X [S*Dm];           // x as half, [S][4096]
__device__ __half g_W6[NQKV*Dm];        // wq|wk|wv transposed: [6144][4096]
__device__ __half g_Wo[Dm*NQ];          // wo transposed: [4096][4096]

// ---------------------------------------------------------------------------
// helpers
// ---------------------------------------------------------------------------
__device__ __forceinline__ void mma_f16(float c[4], const unsigned a[4],
                                        unsigned b0, unsigned b1) {
    asm volatile(
        "mma.sync.aligned.m16n8k16.row.col.f32.f16.f16.f32 "
        "{%0,%1,%2,%3}, {%4,%5,%6,%7}, {%8,%9}, {%0,%1,%2,%3};"
        : "+f"(c[0]), "+f"(c[1]), "+f"(c[2]), "+f"(c[3])
        : "r"(a[0]), "r"(a[1]), "r"(a[2]), "r"(a[3]), "r"(b0), "r"(b1));
}

__device__ __forceinline__ void ldsm4(unsigned& r0, unsigned& r1,
                                      unsigned& r2, unsigned& r3, uint32_t addr) {
    asm volatile("ldmatrix.sync.aligned.m8n8.x4.shared.b16 {%0,%1,%2,%3}, [%4];"
                 : "=r"(r0), "=r"(r1), "=r"(r2), "=r"(r3) : "r"(addr));
}

__device__ __forceinline__ void cp16(uint32_t dst, const void* src) {
    asm volatile("cp.async.cg.shared.global [%0], [%1], 16;\n" :: "r"(dst), "l"(src));
}
__device__ __forceinline__ void cp_commit() {
    asm volatile("cp.async.commit_group;\n");
}
template<int N> __device__ __forceinline__ void cp_wait() {
    asm volatile("cp.async.wait_group %0;\n" :: "n"(N));
}

// ---------------------------------------------------------------------------
// Mega-prep: one launch does x->half and all 4 weight transposes.
// ---------------------------------------------------------------------------
#define RB_WQ 16384
#define RB_WK 4096
#define RB_WV 4096
#define RB_WO 16384
#define RB_X  2048
#define PREP_BLOCKS (RB_WQ + RB_WK + RB_WV + RB_WO + RB_X)

__device__ __forceinline__ void transp_f2h(const float* __restrict__ src,
                                           __half* __restrict__ dst,
                                           int R, int C, int bx, int by, int tid,
                                           float (*tile)[33]) {
    int c0 = bx*32, r0 = by*32;
    int x = tid & 31, y = tid >> 5;
    #pragma unroll
    for (int i = y; i < 32; i += 8)
        tile[i][x] = src[(size_t)(r0 + i) * C + c0 + x];
    __syncthreads();
    #pragma unroll
    for (int i = y; i < 32; i += 8)
        dst[(size_t)(c0 + i) * R + r0 + x] = __float2half_rn(tile[x][i]);
}

__global__ __launch_bounds__(256)
void prep_kernel(const float* __restrict__ x,
                 const float* __restrict__ wq, const float* __restrict__ wk,
                 const float* __restrict__ wv, const float* __restrict__ wo,
                 __half* __restrict__ Xh, __half* __restrict__ W6,
                 __half* __restrict__ Wot) {
    __shared__ float tile[32][33];
    int bid = blockIdx.x;
    int tid = threadIdx.x;
    if (bid < RB_WQ) {
        transp_f2h(wq, W6, Dm, NQ, bid % 128, bid / 128, tid, tile);
        return;
    }
    bid -= RB_WQ;
    if (bid < RB_WK) {
        transp_f2h(wk, W6 + (size_t)NQ*Dm, Dm, NKV, bid % 32, bid / 32, tid, tile);
        return;
    }
    bid -= RB_WK;
    if (bid < RB_WV) {
        transp_f2h(wv, W6 + (size_t)(NQ+NKV)*Dm, Dm, NKV, bid % 32, bid / 32, tid, tile);
        return;
    }
    bid -= RB_WV;
    if (bid < RB_WO) {
        transp_f2h(wo, Wot, NQ, Dm, bid % 128, bid / 128, tid, tile);
        return;
    }
    bid -= RB_WO;
    {
        const float4* src4 = (const float4*)x;
        #pragma unroll
        for (int j = 0; j < 4; j++) {
            int i = bid*1024 + tid + j*256;
            float4 v = src4[i];
            *(__half2*)&Xh[4*i]     = __floats2half2_rn(v.x, v.y);
            *(__half2*)&Xh[4*i + 2] = __floats2half2_rn(v.z, v.w);
        }
    }
}

// ---------------------------------------------------------------------------
// fp16 tensor-core GEMM. 128x128 CTA tile, BK=64 per stage, 3-stage cp.async
// ring, XOR-swizzled 128B rows (no pad), ldmatrix fragments. 8 warps 64x32.
// 2 CTAs/SM (96KB smem/CTA, regs capped 128). Halved barrier frequency vs
// BK=32 — attacks the barrier-convoy that pinned tensor% at ~47.
// mode 0: fp32 C out. mode 1: fused QKV epilogue (RoPE Q/K, V transposed).
// Requires M%128==0, N%128==0, K%64==0, K/64 >= 3.
// ---------------------------------------------------------------------------
#define TILE_BYTES 16384                 // 128 rows x 128 B (A or B)
#define STAGE_BYTES (2*TILE_BYTES)       // 32768
#define GSTAGES 3
#define GEMM_SMEM (GSTAGES*STAGE_BYTES)  // 98304 B

__global__ __launch_bounds__(256, 2)
void gemm_f16(int M, int N, int K,
              const __half* __restrict__ A,
              const __half* __restrict__ Bt,
              void* __restrict__ Cv, int mode,
              __half* __restrict__ Qp, __half* __restrict__ Kp,
              __half* __restrict__ Vtp,
              const float* __restrict__ fc, const float* __restrict__ fs) {
    extern __shared__ __half smh[];
    const uint32_t smemBase = (uint32_t)__cvta_generic_to_shared(smh);

    const int tid  = threadIdx.x;
    const int lane = tid & 31;
    const int wid  = tid >> 5;
    const int gid  = lane >> 2;
    const int tig  = lane & 3;
    const int warpM = wid >> 2;   // 0..1
    const int warpN = wid & 3;    // 0..3
    const int m0 = warpM*64;
    const int n0 = warpN*32;

    // ldmatrix lane geometry (XOR-swizzled rows of 8 16B-chunks)
    const int g8 = lane >> 3, r8 = lane & 7;
    const int rA   = ((g8 & 1) << 3) + r8;     // A: row within 16-row frag
    const int cA   = g8 >> 1;                  // A: 16B-chunk base (0/1)
    const int rB   = ((g8 >> 1) << 3) + r8;    // B: row within 16-row pair
    const int cB   = g8 & 1;

    const int bx = blockIdx.x;
    const int by = blockIdx.y;

    const __half* Abase = A  + (size_t)(by*128) * K;
    const __half* Bbase = Bt + (size_t)(bx*128) * K;

    // one k-tile (64 halves = 128B per row): 1024 chunks each for A and B
    auto issue_tile = [&](int t) {
        const int slot = t % GSTAGES;
        const uint32_t stA = smemBase + slot*STAGE_BYTES;
        const uint32_t stB = stA + TILE_BYTES;
        const __half* Ag = Abase + t*64;
        const __half* Bg = Bbase + t*64;
        #pragma unroll
        for (int j = 0; j < 4; j++) {
            int e = tid + j*256;             // 0..1023
            int row = e >> 3, ch = e & 7;
            cp16(stA + row*128 + ((ch ^ (row & 7)) << 4),
                 Ag + (size_t)row*K + ch*8);
        }
        #pragma unroll
        for (int j = 0; j < 4; j++) {
            int e = tid + j*256;
            int row = e >> 3, ch = e & 7;
            cp16(stB + row*128 + ((ch ^ (row & 7)) << 4),
                 Bg + (size_t)row*K + ch*8);
        }
    };

    float c[4][4][4];
    #pragma unroll
    for (int i = 0; i < 4; i++)
        #pragma unroll
        for (int j = 0; j < 4; j++)
            #pragma unroll
            for (int r = 0; r < 4; r++) c[i][j][r] = 0.f;

    const int nt = K / 64;

    issue_tile(0); cp_commit();
    issue_tile(1); cp_commit();

    for (int t = 0; t < nt; t++) {
        cp_wait<1>();
        __syncthreads();

        if (t + 2 < nt) issue_tile(t + 2);
        cp_commit();

        const int slot = t % GSTAGES;
        const uint32_t slotA = smemBase + slot*STAGE_BYTES;
        const uint32_t slotB = slotA + TILE_BYTES;

        #pragma unroll
        for (int hp = 0; hp < 2; hp++) {       // two 32-k halves of the tile
            unsigned af[2][4][4], bf[2][4][2];
            #pragma unroll
            for (int hh = 0; hh < 2; hh++) {
                const int k16 = hp*2 + hh;     // 16-k step index 0..3
                #pragma unroll
                for (int mf = 0; mf < 4; mf++) {
                    int r = m0 + mf*16 + rA;
                    ldsm4(af[hh][mf][0], af[hh][mf][1],
                          af[hh][mf][2], af[hh][mf][3],
                          slotA + r*128 + (((k16*2 + cA) ^ (r & 7)) << 4));
                }
                #pragma unroll
                for (int nf2 = 0; nf2 < 4; nf2 += 2) {
                    int r = n0 + nf2*8 + rB;
                    ldsm4(bf[hh][nf2][0], bf[hh][nf2][1],
                          bf[hh][nf2+1][0], bf[hh][nf2+1][1],
                          slotB + r*128 + (((k16*2 + cB) ^ (r & 7)) << 4));
                }
            }
            #pragma unroll
            for (int hh = 0; hh < 2; hh++)
                #pragma unroll
                for (int mf = 0; mf < 4; mf++)
                    #pragma unroll
                    for (int nf = 0; nf < 4; nf++)
                        mma_f16(c[mf][nf], af[hh][mf],
                                bf[hh][nf][0], bf[hh][nf][1]);
        }
    }

    // ---- epilogue ----
    if (mode == 0) {
        float* Cf = (float*)Cv;
        #pragma unroll
        for (int mf = 0; mf < 4; mf++) {
            int row0 = by*128 + m0 + mf*16 + gid;
            #pragma unroll
            for (int nf = 0; nf < 4; nf++) {
                int col = bx*128 + n0 + nf*8 + tig*2;
                *(float2*)&Cf[(size_t)row0 * N + col] =
                    make_float2(c[mf][nf][0], c[mf][nf][1]);
                *(float2*)&Cf[(size_t)(row0+8) * N + col] =
                    make_float2(c[mf][nf][2], c[mf][nf][3]);
            }
        }
    } else {
        #pragma unroll
        for (int mf = 0; mf < 4; mf++) {
            int s0 = by*128 + m0 + mf*16 + gid;
            int s1 = s0 + 8;
            #pragma unroll
            for (int nf = 0; nf < 4; nf++) {
                int gc = bx*128 + n0 + nf*8 + tig*2;
                float v0 = c[mf][nf][0], v1 = c[mf][nf][1];
                float v2 = c[mf][nf][2], v3 = c[mf][nf][3];
                if (gc < NQ) {                      // Q with RoPE
                    int i = (gc & 127) >> 1;
                    float c0 = fc[s0*64+i], sn0 = fs[s0*64+i];
                    float c1 = fc[s1*64+i], sn1 = fs[s1*64+i];
                    *(__half2*)&Qp[(size_t)s0*NQ + gc] =
                        __floats2half2_rn(v0*c0 - v1*sn0, v0*sn0 + v1*c0);
                    *(__half2*)&Qp[(size_t)s1*NQ + gc] =
                        __floats2half2_rn(v2*c1 - v3*sn1, v2*sn1 + v3*c1);
                } else if (gc < NQ + NKV) {         // K with RoPE
                    int d = gc - NQ;
                    int i = (d & 127) >> 1;
                    float c0 = fc[s0*64+i], sn0 = fs[s0*64+i];
                    float c1 = fc[s1*64+i], sn1 = fs[s1*64+i];
                    *(__half2*)&Kp[(size_t)s0*NKV + d] =
                        __floats2half2_rn(v0*c0 - v1*sn0, v0*sn0 + v1*c0);
                    *(__half2*)&Kp[(size_t)s1*NKV + d] =
                        __floats2half2_rn(v2*c1 - v3*sn1, v2*sn1 + v3*c1);
                } else {                            // V, transposed store
                    int d = gc - (NQ + NKV);
                    Vtp[(size_t)d*S + s0]     = __float2half_rn(v0);
                    Vtp[(size_t)(d+1)*S + s0] = __float2half_rn(v1);
                    Vtp[(size_t)d*S + s1]     = __float2half_rn(v2);
                    Vtp[(size_t)(d+1)*S + s1] = __float2half_rn(v3);
                }
            }
        }
    }
}

// ---------------------------------------------------------------------------
// Flash attention, fp16 MMA + ldmatrix. BQ=128, BKV=64. 8 warps. (R11 version)
// ---------------------------------------------------------------------------
#define KP 136
#define VP 72
#define PP 72
#define KVT (64*KP)
#define VTT (128*VP)
#define PS_OFF (2*KVT + 2*VTT)
#define FLASH_SMEM ((PS_OFF + 128*PP) * 2)   // 90112 B

__global__ __launch_bounds__(256)
void flash_f16(const __half* __restrict__ Q,
               const __half* __restrict__ K,
               const __half* __restrict__ Vt,
               __half* __restrict__ O) {
    extern __shared__ __half smh[];
    __half* Ks  = smh;
    __half* Ps  = smh + PS_OFF;

    const int qb  = gridDim.x - 1 - blockIdx.x;
    const int h   = blockIdx.y;
    const int kh  = h >> 2;
    const int tid = threadIdx.x;
    const int lane = tid & 31;
    const int wid  = tid >> 5;
    const int gid  = lane >> 2;
    const int tig  = lane & 3;
    const int m0   = wid * 16;
    const float scale = 0.08838834764831845f;

    const uint32_t smemBase = (uint32_t)__cvta_generic_to_shared(smh);
    const __half* Vkh = Vt + (size_t)(kh*HD) * S;

    const int g8 = lane >> 3, r8 = lane & 7;
    const int laneAK = ((((g8 & 1) << 3) + r8) * KP + ((g8 >> 1) << 3)) * 2;
    const int laneBK = ((((g8 >> 1) << 3) + r8) * KP + ((g8 & 1) << 3)) * 2;
    const int laneAP = ((((g8 & 1) << 3) + r8) * PP + ((g8 >> 1) << 3)) * 2;
    const int laneBV = ((((g8 >> 1) << 3) + r8) * VP + ((g8 & 1) << 3)) * 2;

    #pragma unroll
    for (int i = 0; i < 8; i++) {
        int e = tid + i*256;
        int row = e >> 4;
        int ch  = e & 15;
        *(float4*)&Ks[row*KP + ch*8] =
            *(const float4*)&Q[(size_t)(qb*128 + row)*NQ + h*HD + ch*8];
    }
    __syncthreads();

    unsigned qf[8][4];
    #pragma unroll
    for (int ks = 0; ks < 8; ks++)
        ldsm4(qf[ks][0], qf[ks][1], qf[ks][2], qf[ks][3],
              smemBase + (m0*KP + ks*16)*2 + laneAK);
    __syncthreads();

    float of[16][4];
    #pragma unroll
    for (int n = 0; n < 16; n++)
        #pragma unroll
        for (int r = 0; r < 4; r++) of[n][r] = 0.f;
    float mrow0 = -INFINITY, mrow1 = -INFINITY;
    float lrow0 = 0.f, lrow1 = 0.f;

    const int nkv = 2*qb + 2;

    auto issue_tile = [&](int kb) {
        int buf = kb & 1;
        int kv0 = kb * 64;
        #pragma unroll
        for (int j = 0; j < 4; j++) {
            int e = tid + j*256;
            int row = e >> 4;
            int ch  = e & 15;
            cp16(smemBase + (buf*KVT + row*KP + ch*8)*2,
                 &K[(size_t)(kv0+row)*NKV + kh*HD + ch*8]);
        }
        #pragma unroll
        for (int j = 0; j < 4; j++) {
            int e = tid + j*256;
            int d  = e >> 3;
            int ch = e & 7;
            cp16(smemBase + (2*KVT + buf*VTT + d*VP + ch*8)*2,
                 &Vkh[(size_t)d*S + kv0 + ch*8]);
        }
    };

    issue_tile(0); cp_commit();
    issue_tile(1); cp_commit();

    const int grow0 = qb*128 + m0 + gid;
    const int grow1 = grow0 + 8;

    for (int kb = 0; kb < nkv; kb++) {
        const int buf = kb & 1;
        const int kv0 = kb * 64;
        cp_wait<1>();
        __syncthreads();

        float c[8][4];
        #pragma unroll
        for (int nf = 0; nf < 8; nf++)
            #pragma unroll
            for (int r = 0; r < 4; r++) c[nf][r] = 0.f;

        const uint32_t kbAddr = smemBase + buf*KVT*2;
        #pragma unroll
        for (int ks = 0; ks < 8; ks++) {
            #pragma unroll
            for (int nf2 = 0; nf2 < 8; nf2 += 2) {
                unsigned b0, b1, b2, b3;
                ldsm4(b0, b1, b2, b3, kbAddr + (nf2*8*KP + ks*16)*2 + laneBK);
                mma_f16(c[nf2],   qf[ks], b0, b1);
                mma_f16(c[nf2+1], qf[ks], b2, b3);
            }
        }

        const bool needmask = (kb >= 2*qb);
        #pragma unroll
        for (int nf = 0; nf < 8; nf++) {
            int gc = kv0 + nf*8 + 2*tig;
            c[nf][0] *= scale; c[nf][1] *= scale;
            c[nf][2] *= scale; c[nf][3] *= scale;
            if (needmask) {
                if (gc   > grow0) c[nf][0] = -INFINITY;
                if (gc+1 > grow0) c[nf][1] = -INFINITY;
                if (gc   > grow1) c[nf][2] = -INFINITY;
                if (gc+1 > grow1) c[nf][3] = -INFINITY;
            }
        }

        float mx0 = -INFINITY, mx1 = -INFINITY;
        #pragma unroll
        for (int nf = 0; nf < 8; nf++) {
            mx0 = fmaxf(mx0, fmaxf(c[nf][0], c[nf][1]));
            mx1 = fmaxf(mx1, fmaxf(c[nf][2], c[nf][3]));
        }
        mx0 = fmaxf(mx0, __shfl_xor_sync(0xffffffffu, mx0, 1));
        mx0 = fmaxf(mx0, __shfl_xor_sync(0xffffffffu, mx0, 2));
        mx1 = fmaxf(mx1, __shfl_xor_sync(0xffffffffu, mx1, 1));
        mx1 = fmaxf(mx1, __shfl_xor_sync(0xffffffffu, mx1, 2));

        float mn0 = fmaxf(mrow0, mx0);
        float mn1 = fmaxf(mrow1, mx1);
        float a0 = __expf(mrow0 - mn0);
        float a1 = __expf(mrow1 - mn1);
        mrow0 = mn0; mrow1 = mn1;

        float s0 = 0.f, s1 = 0.f;
        #pragma unroll
        for (int nf = 0; nf < 8; nf++) {
            c[nf][0] = __expf(c[nf][0] - mn0);
            c[nf][1] = __expf(c[nf][1] - mn0);
            c[nf][2] = __expf(c[nf][2] - mn1);
            c[nf][3] = __expf(c[nf][3] - mn1);
            s0 += c[nf][0] + c[nf][1];
            s1 += c[nf][2] + c[nf][3];
        }
        s0 += __shfl_xor_sync(0xffffffffu, s0, 1);
        s0 += __shfl_xor_sync(0xffffffffu, s0, 2);
        s1 += __shfl_xor_sync(0xffffffffu, s1, 1);
        s1 += __shfl_xor_sync(0xffffffffu, s1, 2);
        lrow0 = lrow0*a0 + s0;
        lrow1 = lrow1*a1 + s1;

        #pragma unroll
        for (int nf = 0; nf < 16; nf++) {
            of[nf][0] *= a0; of[nf][1] *= a0;
            of[nf][2] *= a1; of[nf][3] *= a1;
        }

        {
            __half* pr0 = Ps + (m0+gid)*PP + 2*tig;
            __half* pr1 = pr0 + 8*PP;
            #pragma unroll
            for (int nf = 0; nf < 8; nf++) {
                *(__half2*)(pr0 + nf*8) = __floats2half2_rn(c[nf][0], c[nf][1]);
                *(__half2*)(pr1 + nf*8) = __floats2half2_rn(c[nf][2], c[nf][3]);
            }
        }
        __syncwarp();

        const uint32_t psAddr = smemBase + PS_OFF*2;
        const uint32_t vbAddr = smemBase + (2*KVT + buf*VTT)*2;
        #pragma unroll
        for (int ks = 0; ks < 4; ks++) {
            unsigned a[4];
            ldsm4(a[0], a[1], a[2], a[3],
                  psAddr + (m0*PP + ks*16)*2 + laneAP);
            #pragma unroll
            for (int nf2 = 0; nf2 < 16; nf2 += 2) {
                unsigned b0, b1, b2, b3;
                ldsm4(b0, b1, b2, b3, vbAddr + (nf2*8*VP + ks*16)*2 + laneBV);
                mma_f16(of[nf2],   a, b0, b1);
                mma_f16(of[nf2+1], a, b2, b3);
            }
        }

        __syncthreads();
        if (kb + 2 < nkv) issue_tile(kb + 2);
        cp_commit();
    }

    float inv0 = 1.f / lrow0;
    float inv1 = 1.f / lrow1;
    #pragma unroll
    for (int nf = 0; nf < 16; nf++) {
        int col = h*HD + nf*8 + 2*tig;
        *(__half2*)&O[(size_t)grow0 * NQ + col] =
            __floats2half2_rn(of[nf][0]*inv0, of[nf][1]*inv0);
        *(__half2*)&O[(size_t)grow1 * NQ + col] =
            __floats2half2_rn(of[nf][2]*inv1, of[nf][3]*inv1);
    }
}

// ---------------------------------------------------------------------------
// Launch
// ---------------------------------------------------------------------------
extern "C" void kernel_launch(void* const* d_in, const int* in_sizes, int n_in,
                              void* d_out, int out_size) {
    const float* x  = (const float*)d_in[0];
    const float* fc = (const float*)d_in[1];
    const float* fs = (const float*)d_in[2];
    const float* wq = (const float*)d_in[3];
    const float* wk = (const float*)d_in[4];
    const float* wv = (const float*)d_in[5];
    const float* wo = (const float*)d_in[6];
    float* out = (float*)d_out;

    __half *Q, *K, *Vt, *ATT, *Xh, *W6, *Wot;
    cudaGetSymbolAddress((void**)&Q,   g_Q);
    cudaGetSymbolAddress((void**)&K,   g_K);
    cudaGetSymbolAddress((void**)&Vt,  g_Vt);
    cudaGetSymbolAddress((void**)&ATT, g_attn);
    cudaGetSymbolAddress((void**)&Xh,  g_X);
    cudaGetSymbolAddress((void**)&W6,  g_W6);
    cudaGetSymbolAddress((void**)&Wot, g_Wo);

    cudaFuncSetAttribute(flash_f16,
        cudaFuncAttributeMaxDynamicSharedMemorySize, FLASH_SMEM);
    cudaFuncSetAttribute(gemm_f16,
        cudaFuncAttributeMaxDynamicSharedMemorySize, GEMM_SMEM);

    // 1) Mega-prep (one launch)
    prep_kernel<<<PREP_BLOCKS, 256>>>(x, wq, wk, wv, wo, Xh, W6, Wot);

    // 2) Fused QKV projection + RoPE (+ V transpose)
    gemm_f16<<<dim3(NQKV/128, S/128), 256, GEMM_SMEM>>>(
        S, NQKV, Dm, Xh, W6, nullptr, 1, Q, K, Vt, fc, fs);

    // 3) Causal GQA flash attention
    flash_f16<<<dim3(S/128, HQ), 256, FLASH_SMEM>>>(Q, K, Vt, ATT);

    // 4) Output projection (fp32 out)
    gemm_f16<<<dim3(Dm/128, S/128), 256, GEMM_SMEM>>>(
        S, Dm, NQ, ATT, Wot, out, 0, nullptr, nullptr, nullptr, nullptr, nullptr);
}